// round 3
// baseline (speedup 1.0000x reference)
#include <cuda_runtime.h>
#include <math.h>

// ---------------------------------------------------------------------------
// SoftLabelLoss: loss = max( (1/B) * sum_i [ e[t_i] - dot(soft[t_i], x_i) + lse(x_i) ], 0 )
//   soft[t][c] = 0.8*(c==t) + 0.2*sim[t][c]/rowsum(sim[t]);  e[t] = sum soft*log(soft)
// Fused: every block builds the soft table + entropies in smem, then streams
// logits once (pair-wise, 2-row-deep register prefetch, __ldcs).
// ---------------------------------------------------------------------------

#define MAXBLOCKS 1024
__device__ double g_part[MAXBLOCKS];

// --- cooperative in-block table build (any C) --------------------------------
__device__ __forceinline__ void build_table(const float* __restrict__ sim,
                                            float* s_soft, float* s_ent,
                                            int C, int lane, int warp) {
    for (int t = warp; t < C; t += 32) {
        const float* srow = sim + (size_t)t * C;
        float s = 0.0f;
        for (int c = lane; c < C; c += 32) {
            float v = __ldg(srow + c);
            s_soft[t * C + c] = v;
            s += v;
        }
        #pragma unroll
        for (int o = 16; o; o >>= 1) s += __shfl_xor_sync(0xffffffffu, s, o);
        float inv = 0.2f / s;                 // smoothing folded in
        float p = 0.0f;
        for (int c = lane; c < C; c += 32) {
            float soft = s_soft[t * C + c] * inv + (c == t ? 0.8f : 0.0f);
            s_soft[t * C + c] = soft;
            p += (soft > 0.0f) ? soft * __logf(soft) : 0.0f;
        }
        #pragma unroll
        for (int o = 16; o; o >>= 1) p += __shfl_xor_sync(0xffffffffu, p, o);
        if (lane == 0) s_ent[t] = p;
    }
}

// --- block partial-sum writeback ---------------------------------------------
__device__ __forceinline__ void block_reduce_store(float acc, int lane, int warp,
                                                   double* s_w) {
    double d = (double)acc;
    #pragma unroll
    for (int o = 16; o; o >>= 1) d += __shfl_xor_sync(0xffffffffu, d, o);
    if (lane == 0) s_w[warp] = d;
    __syncthreads();
    if (warp == 0) {
        double v = s_w[lane];
        #pragma unroll
        for (int o = 16; o; o >>= 1) v += __shfl_xor_sync(0xffffffffu, v, o);
        if (lane == 0) g_part[blockIdx.x] = v;
    }
}

// --- main, templated on float2 chunks per row (C even) ------------------------
template<int NCH>
__global__ __launch_bounds__(1024, 1)
void slloss_main_t(const float* __restrict__ logits,
                   const int*   __restrict__ targets,
                   const float* __restrict__ sim,
                   int B, int C) {
    extern __shared__ float smem[];
    float*  s_soft = smem;                       // C*C
    float*  s_ent  = smem + C * C;               // C
    double* s_w    = (double*)(smem + C * C + ((C + 1) & ~1));  // 32 doubles, 8B aligned

    const int tid  = threadIdx.x;
    const int lane = tid & 31;
    const int warp = tid >> 5;

    build_table(sim, s_soft, s_ent, C, lane, warp);
    __syncthreads();

    const int NW = gridDim.x * 32;
    const int gw = blockIdx.x * 32 + warp;
    const int C2 = C >> 1;

    long long per = ((long long)B + NW - 1) / NW;
    long long r0  = (long long)gw * per;
    long long r1  = r0 + per; if (r1 > B) r1 = B;
    if (r0 > B) r0 = B;

    float acc = 0.0f;

    for (long long base = r0; base < r1; base += 32) {
        const int nrows = (int)((r1 - base) < 32 ? (r1 - base) : 32);
        int t32 = (lane < nrows) ? __ldg(targets + base + lane) : 0;
        const float* rp = logits + base * (long long)C;

        int r = 0;
        if (nrows >= 2) {
            float2 cA[NCH], cB[NCH], nA[NCH], nB[NCH];
            #pragma unroll
            for (int k = 0; k < NCH; k++) {
                int j = lane + 32 * k;
                cA[k] = (j < C2) ? __ldcs((const float2*)rp + j) : make_float2(0.f, 0.f);
                cB[k] = (j < C2) ? __ldcs((const float2*)(rp + C) + j) : make_float2(0.f, 0.f);
                nA[k] = make_float2(0.f, 0.f);
                nB[k] = make_float2(0.f, 0.f);
            }

            for (; r + 2 <= nrows; r += 2) {
                if (r + 3 < nrows) {
                    const float2* pA = (const float2*)(rp + (long long)(r + 2) * C);
                    const float2* pB = (const float2*)(rp + (long long)(r + 3) * C);
                    #pragma unroll
                    for (int k = 0; k < NCH; k++) {
                        int j = lane + 32 * k;
                        if (j < C2) { nA[k] = __ldcs(pA + j); nB[k] = __ldcs(pB + j); }
                    }
                }

                int t0 = __shfl_sync(0xffffffffu, t32, r);
                int t1 = __shfl_sync(0xffffffffu, t32, r + 1);
                const float2* sw0 = (const float2*)(s_soft + (t0 >= 0 ? t0 : 0) * C);
                const float2* sw1 = (const float2*)(s_soft + (t1 >= 0 ? t1 : 0) * C);

                float se0 = 0.f, dt0 = 0.f, se1 = 0.f, dt1 = 0.f;
                #pragma unroll
                for (int k = 0; k < NCH; k++) {
                    int j = lane + 32 * k;
                    if (j < C2) {
                        float2 x0 = cA[k], w0 = sw0[j];
                        float2 x1 = cB[k], w1 = sw1[j];
                        se0 += __expf(x0.x) + __expf(x0.y);
                        se1 += __expf(x1.x) + __expf(x1.y);
                        dt0 = fmaf(w0.x, x0.x, dt0); dt0 = fmaf(w0.y, x0.y, dt0);
                        dt1 = fmaf(w1.x, x1.x, dt1); dt1 = fmaf(w1.y, x1.y, dt1);
                    }
                }
                #pragma unroll
                for (int o = 16; o; o >>= 1) {
                    se0 += __shfl_xor_sync(0xffffffffu, se0, o);
                    se1 += __shfl_xor_sync(0xffffffffu, se1, o);
                }
                if (t0 >= 0) { acc -= dt0; if (lane == 0) acc += s_ent[t0] + __logf(se0); }
                if (t1 >= 0) { acc -= dt1; if (lane == 0) acc += s_ent[t1] + __logf(se1); }

                #pragma unroll
                for (int k = 0; k < NCH; k++) { cA[k] = nA[k]; cB[k] = nB[k]; }
            }
        }
        // scalar tail (0 or 1 row)
        for (; r < nrows; r++) {
            int t = __shfl_sync(0xffffffffu, t32, r);
            const float* lg = rp + (long long)r * C;
            const float* sw = s_soft + (t >= 0 ? t : 0) * C;
            float se = 0.f, dt = 0.f;
            for (int c = lane; c < C; c += 32) {
                float x = __ldg(lg + c);
                se += __expf(x);
                dt = fmaf(sw[c], x, dt);
            }
            #pragma unroll
            for (int o = 16; o; o >>= 1) se += __shfl_xor_sync(0xffffffffu, se, o);
            if (t >= 0) { acc -= dt; if (lane == 0) acc += s_ent[t] + __logf(se); }
        }
    }

    block_reduce_store(acc, lane, warp, s_w);
}

// --- generic fallback (any C) --------------------------------------------------
__global__ __launch_bounds__(1024, 1)
void slloss_main_gen(const float* __restrict__ logits,
                     const int*   __restrict__ targets,
                     const float* __restrict__ sim,
                     int B, int C) {
    extern __shared__ float smem[];
    float*  s_soft = smem;
    float*  s_ent  = smem + C * C;
    double* s_w    = (double*)(smem + C * C + ((C + 1) & ~1));

    const int tid = threadIdx.x, lane = tid & 31, warp = tid >> 5;
    build_table(sim, s_soft, s_ent, C, lane, warp);
    __syncthreads();

    const int NW = gridDim.x * 32;
    const int gw = blockIdx.x * 32 + warp;
    long long per = ((long long)B + NW - 1) / NW;
    long long r0 = (long long)gw * per;
    long long r1 = r0 + per; if (r1 > B) r1 = B;
    if (r0 > B) r0 = B;

    float acc = 0.0f;
    for (long long row = r0; row < r1; row++) {
        int t = __ldg(&targets[row]);
        if (t < 0) continue;
        const float* lg = logits + (size_t)row * C;
        const float* sw = s_soft + t * C;
        float se = 0.f, dt = 0.f;
        for (int c = lane; c < C; c += 32) {
            float x = __ldg(lg + c);
            se += __expf(x);
            dt = fmaf(sw[c], x, dt);
        }
        #pragma unroll
        for (int o = 16; o; o >>= 1) se += __shfl_xor_sync(0xffffffffu, se, o);
        acc -= dt;
        if (lane == 0) acc += s_ent[t] + __logf(se);
    }
    block_reduce_store(acc, lane, warp, s_w);
}

// --- final: sum block partials, scale, clamp -----------------------------------
__global__ void slloss_final(float* __restrict__ out, int nblocks, int B) {
    double s = 0.0;
    for (int i = threadIdx.x; i < nblocks; i += 32) s += g_part[i];
    #pragma unroll
    for (int o = 16; o; o >>= 1) s += __shfl_xor_sync(0xffffffffu, s, o);
    if (threadIdx.x == 0) {
        double loss = s / (double)B;
        out[0] = (float)(loss > 0.0 ? loss : 0.0);
    }
}

extern "C" void kernel_launch(void* const* d_in, const int* in_sizes, int n_in,
                              void* d_out, int out_size) {
    const float* logits  = (const float*)d_in[0];
    const int*   targets = (const int*)  d_in[1];
    const float* sim     = (const float*)d_in[2];
    float*       out     = (float*)d_out;

    int B = in_sizes[1];
    int C = in_sizes[0] / B;

    int nsm = 148;
    cudaDeviceGetAttribute(&nsm, cudaDevAttrMultiProcessorCount, 0);
    if (nsm > MAXBLOCKS) nsm = MAXBLOCKS;

    size_t smem = (size_t)(C * C + ((C + 1) & ~1)) * sizeof(float) + 32 * sizeof(double);

    int  nch  = ((C >> 1) + 31) / 32;
    bool even = (C & 1) == 0;

    if (even && nch >= 1 && nch <= 4) {
        switch (nch) {
        case 1:
            cudaFuncSetAttribute(slloss_main_t<1>, cudaFuncAttributeMaxDynamicSharedMemorySize, (int)smem);
            slloss_main_t<1><<<nsm, 1024, smem>>>(logits, targets, sim, B, C); break;
        case 2:
            cudaFuncSetAttribute(slloss_main_t<2>, cudaFuncAttributeMaxDynamicSharedMemorySize, (int)smem);
            slloss_main_t<2><<<nsm, 1024, smem>>>(logits, targets, sim, B, C); break;
        case 3:
            cudaFuncSetAttribute(slloss_main_t<3>, cudaFuncAttributeMaxDynamicSharedMemorySize, (int)smem);
            slloss_main_t<3><<<nsm, 1024, smem>>>(logits, targets, sim, B, C); break;
        case 4:
            cudaFuncSetAttribute(slloss_main_t<4>, cudaFuncAttributeMaxDynamicSharedMemorySize, (int)smem);
            slloss_main_t<4><<<nsm, 1024, smem>>>(logits, targets, sim, B, C); break;
        }
    } else {
        cudaFuncSetAttribute(slloss_main_gen, cudaFuncAttributeMaxDynamicSharedMemorySize, (int)smem);
        slloss_main_gen<<<nsm, 1024, smem>>>(logits, targets, sim, B, C);
    }

    slloss_final<<<1, 32>>>(out, nsm, B);
}

// round 4
// speedup vs baseline: 1.1444x; 1.1444x over previous
#include <cuda_runtime.h>
#include <math.h>

// ---------------------------------------------------------------------------
// SoftLabelLoss: loss = max( (1/B) * sum_i [ e[t_i] - dot(soft[t_i], x_i) + lse(x_i) ], 0 )
//   soft[t][c] = 0.8*(c==t) + 0.2*sim[t][c]/rowsum(sim[t]);  e[t] = sum soft*log(soft)
// Single fused kernel: per-block smem table build -> single pass over logits
// (unroll-4 register pipeline) -> deterministic fixed-point atomic finalize.
// ---------------------------------------------------------------------------

#define FXSCALE 4294967296.0   // 2^32

__device__ unsigned long long g_sum  = 0ULL;
__device__ unsigned int       g_done = 0u;

// --- cooperative in-block table build (any C) --------------------------------
__device__ __forceinline__ void build_table(const float* __restrict__ sim,
                                            float* s_soft, float* s_ent,
                                            int C, int lane, int warp) {
    for (int t = warp; t < C; t += 32) {
        const float* srow = sim + (size_t)t * C;
        float s = 0.0f;
        for (int c = lane; c < C; c += 32) {
            float v = __ldg(srow + c);
            s_soft[t * C + c] = v;
            s += v;
        }
        #pragma unroll
        for (int o = 16; o; o >>= 1) s += __shfl_xor_sync(0xffffffffu, s, o);
        float inv = 0.2f / s;                 // smoothing folded in
        float p = 0.0f;
        for (int c = lane; c < C; c += 32) {
            float soft = s_soft[t * C + c] * inv + (c == t ? 0.8f : 0.0f);
            s_soft[t * C + c] = soft;
            p += (soft > 0.0f) ? soft * __logf(soft) : 0.0f;
        }
        #pragma unroll
        for (int o = 16; o; o >>= 1) p += __shfl_xor_sync(0xffffffffu, p, o);
        if (lane == 0) s_ent[t] = p;
    }
}

// --- per-row compute on register buffer ---------------------------------------
template<int NCH>
__device__ __forceinline__ void row_compute(const float2* __restrict__ sw,
                                            const float2 (&x)[NCH],
                                            int lane, int C2,
                                            float& se, float& dt) {
    se = 0.0f; dt = 0.0f;
    #pragma unroll
    for (int k = 0; k < NCH; k++) {
        int j = lane + 32 * k;
        if (j < C2) {
            float2 w = sw[j];
            se += __expf(x[k].x) + __expf(x[k].y);
            dt = fmaf(w.x, x[k].x, dt);
            dt = fmaf(w.y, x[k].y, dt);
        }
    }
}

template<int NCH>
__device__ __forceinline__ void ld_row(float2 (&b)[NCH],
                                       const float* __restrict__ rowp,
                                       int lane, int C2) {
    const float2* p = (const float2*)rowp;
    #pragma unroll
    for (int k = 0; k < NCH; k++) {
        int j = lane + 32 * k;
        b[k] = (j < C2) ? __ldcs(p + j) : make_float2(0.f, 0.f);
    }
}

// --- deterministic fixed-point finalize ----------------------------------------
__device__ __forceinline__ void block_finalize(float acc, int tid, int lane, int warp,
                                               double* s_w, float* out, int B) {
    double d = (double)acc;
    #pragma unroll
    for (int o = 16; o; o >>= 1) d += __shfl_xor_sync(0xffffffffu, d, o);
    if (lane == 0) s_w[warp] = d;
    __syncthreads();
    if (warp == 0) {
        int nw = (blockDim.x + 31) >> 5;
        double v = (lane < nw) ? s_w[lane] : 0.0;
        #pragma unroll
        for (int o = 16; o; o >>= 1) v += __shfl_xor_sync(0xffffffffu, v, o);
        if (lane == 0) {
            long long q = __double2ll_rn(v * FXSCALE);
            atomicAdd(&g_sum, (unsigned long long)q);
            __threadfence();
            unsigned int tk = atomicAdd(&g_done, 1u);
            if (tk == gridDim.x - 1) {            // last block: finish + reset
                unsigned long long raw = atomicAdd(&g_sum, 0ULL);
                double loss = ((double)(long long)raw / FXSCALE) / (double)B;
                out[0] = (float)(loss > 0.0 ? loss : 0.0);
                g_sum  = 0ULL;
                g_done = 0u;
                __threadfence();
            }
        }
    }
}

// --- main, templated on float2 chunks per row (C even) -------------------------
template<int NCH>
__global__ __launch_bounds__(1024, 1)
void slloss_fused(const float* __restrict__ logits,
                  const int*   __restrict__ targets,
                  const float* __restrict__ sim,
                  float* __restrict__ out,
                  int B, int C) {
    extern __shared__ float smem[];
    float*  s_soft = smem;                                      // C*C
    float*  s_ent  = smem + C * C;                              // C
    double* s_w    = (double*)(smem + C * C + ((C + 1) & ~1));  // 32 doubles

    const int tid  = threadIdx.x;
    const int lane = tid & 31;
    const int warp = tid >> 5;

    build_table(sim, s_soft, s_ent, C, lane, warp);
    __syncthreads();

    const int NW = gridDim.x * 32;
    const int gw = blockIdx.x * 32 + warp;
    const int C2 = C >> 1;

    long long per = ((long long)B + NW - 1) / NW;
    long long r0  = (long long)gw * per; if (r0 > B) r0 = B;
    long long r1  = r0 + per;            if (r1 > B) r1 = B;

    float acc = 0.0f;

    for (long long base = r0; base < r1; base += 32) {
        const int nrows  = (int)((r1 - base) < 32 ? (r1 - base) : 32);
        const int nrows4 = nrows & ~3;
        int t32 = (lane < nrows) ? __ldg(targets + base + lane) : 0;
        const float* rp = logits + base * (long long)C;

        int r = 0;
        if (nrows4 >= 4) {
            float2 b0[NCH], b1[NCH], b2[NCH], b3[NCH];
            ld_row<NCH>(b0, rp,         lane, C2);
            ld_row<NCH>(b1, rp + C,     lane, C2);
            ld_row<NCH>(b2, rp + 2 * C, lane, C2);
            ld_row<NCH>(b3, rp + 3 * C, lane, C2);

            for (; r < nrows4; r += 4) {
                bool more = (r + 4 < nrows4);
                float se, dt; int t;

                #define DO_ROW(BUF, RR)                                                     \
                {                                                                           \
                    t = __shfl_sync(0xffffffffu, t32, (RR));                                \
                    const float2* sw = (const float2*)(s_soft + (t >= 0 ? t : 0) * C);      \
                    row_compute<NCH>(sw, BUF, lane, C2, se, dt);                            \
                    if (more) ld_row<NCH>(BUF, rp + (long long)((RR) + 4) * C, lane, C2);   \
                    _Pragma("unroll")                                                       \
                    for (int o = 16; o; o >>= 1) se += __shfl_xor_sync(0xffffffffu, se, o); \
                    if (t >= 0) {                                                           \
                        acc -= dt;                                                          \
                        if (lane == 0) acc += s_ent[t] + __logf(se);                        \
                    }                                                                       \
                }

                DO_ROW(b0, r)
                DO_ROW(b1, r + 1)
                DO_ROW(b2, r + 2)
                DO_ROW(b3, r + 3)
                #undef DO_ROW
            }
        }
        // scalar tail (<4 rows)
        for (; r < nrows; r++) {
            int t = __shfl_sync(0xffffffffu, t32, r);
            const float* lg = rp + (long long)r * C;
            const float* sw = s_soft + (t >= 0 ? t : 0) * C;
            float se = 0.f, dt = 0.f;
            for (int c = lane; c < C; c += 32) {
                float x = __ldg(lg + c);
                se += __expf(x);
                dt = fmaf(sw[c], x, dt);
            }
            #pragma unroll
            for (int o = 16; o; o >>= 1) se += __shfl_xor_sync(0xffffffffu, se, o);
            if (t >= 0) { acc -= dt; if (lane == 0) acc += s_ent[t] + __logf(se); }
        }
    }

    block_finalize(acc, tid, lane, warp, s_w, out, B);
}

// --- generic fallback (any C) ----------------------------------------------------
__global__ __launch_bounds__(1024, 1)
void slloss_fused_gen(const float* __restrict__ logits,
                      const int*   __restrict__ targets,
                      const float* __restrict__ sim,
                      float* __restrict__ out,
                      int B, int C) {
    extern __shared__ float smem[];
    float*  s_soft = smem;
    float*  s_ent  = smem + C * C;
    double* s_w    = (double*)(smem + C * C + ((C + 1) & ~1));

    const int tid = threadIdx.x, lane = tid & 31, warp = tid >> 5;
    build_table(sim, s_soft, s_ent, C, lane, warp);
    __syncthreads();

    const int NW = gridDim.x * 32;
    const int gw = blockIdx.x * 32 + warp;
    long long per = ((long long)B + NW - 1) / NW;
    long long r0 = (long long)gw * per; if (r0 > B) r0 = B;
    long long r1 = r0 + per;            if (r1 > B) r1 = B;

    float acc = 0.0f;
    for (long long row = r0; row < r1; row++) {
        int t = __ldg(&targets[row]);
        if (t < 0) continue;
        const float* lg = logits + (size_t)row * C;
        const float* sw = s_soft + t * C;
        float se = 0.f, dt = 0.f;
        for (int c = lane; c < C; c += 32) {
            float x = __ldg(lg + c);
            se += __expf(x);
            dt = fmaf(sw[c], x, dt);
        }
        #pragma unroll
        for (int o = 16; o; o >>= 1) se += __shfl_xor_sync(0xffffffffu, se, o);
        acc -= dt;
        if (lane == 0) acc += s_ent[t] + __logf(se);
    }
    block_finalize(acc, tid, lane, warp, s_w, out, B);
}

extern "C" void kernel_launch(void* const* d_in, const int* in_sizes, int n_in,
                              void* d_out, int out_size) {
    const float* logits  = (const float*)d_in[0];
    const int*   targets = (const int*)  d_in[1];
    const float* sim     = (const float*)d_in[2];
    float*       out     = (float*)d_out;

    int B = in_sizes[1];
    int C = in_sizes[0] / B;

    int nsm = 148;
    cudaDeviceGetAttribute(&nsm, cudaDevAttrMultiProcessorCount, 0);

    size_t smem = (size_t)(C * C + ((C + 1) & ~1)) * sizeof(float) + 32 * sizeof(double);

    int  nch  = ((C >> 1) + 31) / 32;
    bool even = (C & 1) == 0;

    if (even && nch >= 1 && nch <= 4) {
        switch (nch) {
        case 1:
            cudaFuncSetAttribute(slloss_fused<1>, cudaFuncAttributeMaxDynamicSharedMemorySize, (int)smem);
            slloss_fused<1><<<nsm, 1024, smem>>>(logits, targets, sim, out, B, C); break;
        case 2:
            cudaFuncSetAttribute(slloss_fused<2>, cudaFuncAttributeMaxDynamicSharedMemorySize, (int)smem);
            slloss_fused<2><<<nsm, 1024, smem>>>(logits, targets, sim, out, B, C); break;
        case 3:
            cudaFuncSetAttribute(slloss_fused<3>, cudaFuncAttributeMaxDynamicSharedMemorySize, (int)smem);
            slloss_fused<3><<<nsm, 1024, smem>>>(logits, targets, sim, out, B, C); break;
        case 4:
            cudaFuncSetAttribute(slloss_fused<4>, cudaFuncAttributeMaxDynamicSharedMemorySize, (int)smem);
            slloss_fused<4><<<nsm, 1024, smem>>>(logits, targets, sim, out, B, C); break;
        }
    } else {
        cudaFuncSetAttribute(slloss_fused_gen, cudaFuncAttributeMaxDynamicSharedMemorySize, (int)smem);
        slloss_fused_gen<<<nsm, 1024, smem>>>(logits, targets, sim, out, B, C);
    }
}